// round 12
// baseline (speedup 1.0000x reference)
#include <cuda_runtime.h>
#include <cuda_bf16.h>
#include <math.h>
#include <stdint.h>

#define BB   8
#define SS   16
#define IND  4096
#define HH   32
#define DD   128
#define PASTL 4096
#define KVL  4112
#define MM   128      /* B*S */
#define HD   4096     /* H*D */
#define CHUNK 96
#define NSPLIT 43     /* ceil(4112/96) */
#define KCHUNK 32
#define NCH  (IND / KCHUNK)   /* 128 */
#define KS_QKV 2
#define KS_O   6

static const size_t K_OFF    = (size_t)MM * IND;                 // 524288
static const size_t KV_ELEMS = (size_t)BB * HH * KVL * DD;       // 134742016
static const size_t V_OFF    = K_OFF + KV_ELEMS;

// Scratch (device globals: no allocation allowed)
__device__ float g_q[MM * HD];                  // [bh][s][d]
__device__ float g_attn[MM * HD];               // [m][h*128+d]
__device__ float g_part[(size_t)KS_O * MM * 3 * HD];      // split-K partials
__device__ float g_pacc[(size_t)NSPLIT * 256 * SS * DD];  // flash partial O
__device__ float g_pm[(size_t)NSPLIT * 256 * SS];
__device__ float g_pl[(size_t)NSPLIT * 256 * SS];

// ---------------- helpers ----------------
__device__ __forceinline__ uint32_t smem_u32(const void* p) {
    uint32_t a;
    asm("{ .reg .u64 t; cvta.to.shared.u64 t, %1; cvt.u32.u64 %0, t; }"
        : "=r"(a) : "l"(p));
    return a;
}
__device__ __forceinline__ void ldsm4(uint32_t* r, uint32_t addr) {
    asm volatile("ldmatrix.sync.aligned.m8n8.x4.shared.b16 {%0,%1,%2,%3}, [%4];"
        : "=r"(r[0]), "=r"(r[1]), "=r"(r[2]), "=r"(r[3]) : "r"(addr));
}
__device__ __forceinline__ void mma_bf16(float* d, const uint32_t* a,
                                         const uint32_t* b) {
    asm volatile(
        "mma.sync.aligned.m16n8k16.row.col.f32.bf16.bf16.f32 "
        "{%0,%1,%2,%3}, {%4,%5,%6,%7}, {%8,%9}, {%0,%1,%2,%3};"
        : "+f"(d[0]), "+f"(d[1]), "+f"(d[2]), "+f"(d[3])
        : "r"(a[0]), "r"(a[1]), "r"(a[2]), "r"(a[3]), "r"(b[0]), "r"(b[1]));
}
__device__ __forceinline__ void cpa16(uint32_t dst, const void* src) {
    asm volatile("cp.async.cg.shared.global [%0], [%1], 16;"
                 :: "r"(dst), "l"(src) : "memory");
}

// f32x2 helpers for flash kernel
__device__ __forceinline__ void fma2(unsigned long long& acc,
                                     unsigned long long a, unsigned long long b)
{
    asm("fma.rn.f32x2 %0, %1, %2, %0;" : "+l"(acc) : "l"(a), "l"(b));
}
__device__ __forceinline__ unsigned long long dup2(float x)
{
    unsigned long long r;
    unsigned int u = __float_as_uint(x);
    asm("mov.b64 %0, {%1, %1};" : "=l"(r) : "r"(u));
    return r;
}
__device__ __forceinline__ float2 unpk(unsigned long long v)
{
    unsigned int lo, hi;
    asm("mov.b64 {%0, %1}, %2;" : "=r"(lo), "=r"(hi) : "l"(v));
    return make_float2(__uint_as_float(lo), __uint_as_float(hi));
}

// Convert float4 -> bf16 hi/lo pairs, store (8B each) into 80B-stride rows.
// Row = 32 bf16 (64B data, 80B stride => conflict-free ldmatrix w/o swizzle).
__device__ __forceinline__ void cvt_store80(uint32_t hiBase, uint32_t loBase,
                                            int r, int c4, float4 v) {
    uint32_t h0, h1;
    asm("cvt.rn.bf16x2.f32 %0, %1, %2;" : "=r"(h0) : "f"(v.y), "f"(v.x));
    asm("cvt.rn.bf16x2.f32 %0, %1, %2;" : "=r"(h1) : "f"(v.w), "f"(v.z));
    float hx = __uint_as_float(h0 << 16), hy = __uint_as_float(h0 & 0xFFFF0000u);
    float hz = __uint_as_float(h1 << 16), hw = __uint_as_float(h1 & 0xFFFF0000u);
    float lx = v.x - hx, ly = v.y - hy, lz = v.z - hz, lw = v.w - hw;
    uint32_t l0, l1;
    asm("cvt.rn.bf16x2.f32 %0, %1, %2;" : "=r"(l0) : "f"(ly), "f"(lx));
    asm("cvt.rn.bf16x2.f32 %0, %1, %2;" : "=r"(l1) : "f"(lw), "f"(lz));
    uint32_t off = (uint32_t)(r * 80 + (c4 >> 1) * 16 + (c4 & 1) * 8);
    asm volatile("st.shared.v2.b32 [%0], {%1,%2};" :: "r"(hiBase + off), "r"(h0), "r"(h1));
    asm volatile("st.shared.v2.b32 [%0], {%1,%2};" :: "r"(loBase + off), "r"(l0), "r"(l1));
}

// ---------------------------------------------------------------------------
// bf16x3 MMA GEMM, split-K, NT=64, single fp32 staging, 3 CTAs/SM.
// Y[m,n] = sum_k A[m,k] * W[n,k]. M=128. KCHUNK=32.
// 256 threads = 8 warps (2m x 4n); warp tile 64m x 16n (NA=2).
// Grid (ntiles, KS). Partials -> g_part.
// mode<0: QKV (z = tile/64); mode==3: O-proj (A = g_attn).
// ---------------------------------------------------------------------------
template<int KS>
__global__ __launch_bounds__(256, 3) void gemm_mma(
    const float* __restrict__ A,
    const float* __restrict__ W0, const float* __restrict__ W1,
    const float* __restrict__ W2,
    int NTOT, int mode)
{
    constexpr int NT  = 64;
    constexpr int WN  = 16;              // n per warp
    constexpr int NA  = 2;               // n-atoms per warp
    constexpr int ASTG = 128 * 32 * 4;   // fp32 staging, A chunk (16KB)
    constexpr int WSTG = NT * 32 * 4;    // fp32 staging, W chunk (8KB)

    extern __shared__ char dsm[];
    uint32_t dbase = (smem_u32(dsm) + 1023) & ~1023u;
    uint32_t stg = dbase;                     // single fp32 staging
    uint32_t aHi = dbase + ASTG + WSTG;       // bf16 buffers
    uint32_t aLo = aHi + 128 * 80;
    uint32_t wHi = aLo + 128 * 80;
    uint32_t wLo = wHi + NT * 80;

    int t = threadIdx.x, wid = t >> 5, lane = t & 31;
    int tile  = blockIdx.x;
    int split = blockIdx.y;
    int z  = (mode < 0) ? (tile >> 6) : 0;
    int n0 = (mode < 0) ? ((tile & 63) * NT) : tile * NT;
    const float* Ap = (mode == 3) ? g_attn : A;
    const float* W  = (z == 0) ? W0 : (z == 1) ? W1 : W2;

    int c_beg = (split * NCH) / KS;
    int c_end = ((split + 1) * NCH) / KS;

    int warp_m = wid & 1, warp_n = wid >> 1;

    float acc[4][NA][4];
#pragma unroll
    for (int i = 0; i < 4; i++)
#pragma unroll
        for (int j = 0; j < NA; j++)
#pragma unroll
            for (int q = 0; q < 4; q++) acc[i][j][q] = 0.f;

    int c4 = t & 7, r0 = t >> 3;   // f4 col (8 per 32-col row), row base (32/pass)
    int a_rowin = lane & 15, a_kb = lane >> 4;
    int b_sub = lane >> 3, b_rowin = lane & 7;
    int b_kb = b_sub & 1, b_half = (b_sub >> 1) & 1;

    // cp.async issue for chunk ch into the single staging buffer.
    auto issue_chunk = [&](int ch) {
        if (ch < c_end) {
            int k0 = ch * KCHUNK;
#pragma unroll
            for (int j = 0; j < 4; j++)
                cpa16(stg + (uint32_t)((r0 + 32 * j) * 128 + c4 * 16),
                      Ap + (size_t)(r0 + 32 * j) * IND + k0 + c4 * 4);
#pragma unroll
            for (int j = 0; j < 2; j++)
                cpa16(stg + ASTG + (uint32_t)((r0 + 32 * j) * 128 + c4 * 16),
                      W + (size_t)(n0 + r0 + 32 * j) * IND + k0 + c4 * 4);
        }
        asm volatile("cp.async.commit_group;" ::: "memory");
    };

    issue_chunk(c_beg);

    for (int ch = c_beg; ch < c_end; ch++) {
        asm volatile("cp.async.wait_group 0;" ::: "memory");
        __syncthreads();   // staging(ch) visible; bf16 buf free (MMA ch-1 done)

        // convert staging fp32 -> bf16 hi/lo smem
#pragma unroll
        for (int j = 0; j < 4; j++) {
            float4 v;
            uint32_t sa = stg + (uint32_t)((r0 + 32 * j) * 128 + c4 * 16);
            asm volatile("ld.shared.v4.f32 {%0,%1,%2,%3}, [%4];"
                : "=f"(v.x), "=f"(v.y), "=f"(v.z), "=f"(v.w) : "r"(sa));
            cvt_store80(aHi, aLo, r0 + 32 * j, c4, v);
        }
#pragma unroll
        for (int j = 0; j < 2; j++) {
            float4 v;
            uint32_t sa = stg + ASTG + (uint32_t)((r0 + 32 * j) * 128 + c4 * 16);
            asm volatile("ld.shared.v4.f32 {%0,%1,%2,%3}, [%4];"
                : "=f"(v.x), "=f"(v.y), "=f"(v.z), "=f"(v.w) : "r"(sa));
            cvt_store80(wHi, wLo, r0 + 32 * j, c4, v);
        }
        __syncthreads();   // bf16 ready; staging fully read

        issue_chunk(ch + 1);  // refill staging behind the MMAs

#pragma unroll
        for (int ks = 0; ks < 2; ks++) {
            uint32_t bh[NA][2], bl[NA][2];
            {
                int row = warp_n * WN + b_half * 8 + b_rowin;
                uint32_t o = (uint32_t)(row * 80 + (ks * 2 + b_kb) * 16);
                uint32_t r4[4];
                ldsm4(r4, wHi + o);
                bh[0][0] = r4[0]; bh[0][1] = r4[1];
                bh[1][0] = r4[2]; bh[1][1] = r4[3];
                ldsm4(r4, wLo + o);
                bl[0][0] = r4[0]; bl[0][1] = r4[1];
                bl[1][0] = r4[2]; bl[1][1] = r4[3];
            }
#pragma unroll
            for (int i = 0; i < 4; i++) {
                uint32_t ah[4], al[4];
                int row = warp_m * 64 + i * 16 + a_rowin;
                uint32_t o = (uint32_t)(row * 80 + (ks * 2 + a_kb) * 16);
                ldsm4(ah, aHi + o);
                ldsm4(al, aLo + o);
#pragma unroll
                for (int j = 0; j < NA; j++) {
                    mma_bf16(acc[i][j], ah, bh[j]);
                    mma_bf16(acc[i][j], ah, bl[j]);
                    mma_bf16(acc[i][j], al, bh[j]);
                }
            }
        }
    }

    // ---- epilogue: fragments -> g_part partials ----
    int g = lane >> 2, tq = lane & 3;
#pragma unroll
    for (int i = 0; i < 4; i++) {
#pragma unroll
        for (int j = 0; j < NA; j++) {
            int col = z * 4096 + n0 + warp_n * WN + j * 8 + tq * 2;
#pragma unroll
            for (int half = 0; half < 2; half++) {
                int m = warp_m * 64 + i * 16 + g + half * 8;
                *(float2*)&g_part[(size_t)(split * MM + m) * NTOT + col] =
                    make_float2(acc[i][j][2 * half], acc[i][j][2 * half + 1]);
            }
        }
    }
}

// ---------------------------------------------------------------------------
// Reduce QKV split-K partials (KS_QKV) and route. 393216 float4s total,
// processed in two half-launches (base = f4 offset) so flash is launch #4.
// ---------------------------------------------------------------------------
__global__ __launch_bounds__(256) void reduce_qkv_k(float* __restrict__ dout,
                                                    int base)
{
    int i = base + blockIdx.x * 256 + threadIdx.x;  // float4 index
    int m = i / 3072, c = i - m * 3072;
    const float4* p = (const float4*)g_part;
    float4 s = p[(size_t)m * 3072 + c];
#pragma unroll
    for (int sp = 1; sp < KS_QKV; sp++) {
        float4 a = p[(size_t)(sp * MM + m) * 3072 + c];
        s.x += a.x; s.y += a.y; s.z += a.z; s.w += a.w;
    }
    int n  = c * 4;
    int z  = n >> 12, nl = n & 4095;
    int h  = nl >> 7, dd = nl & 127;
    int b  = m >> 4, sq = m & 15;
    if (z == 0) {
        *(float4*)&g_q[((size_t)(b * HH + h) * SS + sq) * DD + dd] = s;
    } else {
        size_t off = (z == 1) ? K_OFF : V_OFF;
        *(float4*)&dout[off + ((size_t)(b * HH + h) * KVL + PASTL + sq) * DD + dd] = s;
    }
}

// Reduce O-proj split-K partials (KS_O). 131072 float4s.
__global__ __launch_bounds__(256) void reduce_o_k(float* __restrict__ dout)
{
    int i = blockIdx.x * 256 + threadIdx.x;
    int m = i / 1024, c = i - m * 1024;
    const float4* p = (const float4*)g_part;
    float4 s = p[(size_t)m * 1024 + c];
#pragma unroll
    for (int sp = 1; sp < KS_O; sp++) {
        float4 a = p[(size_t)(sp * MM + m) * 1024 + c];
        s.x += a.x; s.y += a.y; s.z += a.z; s.w += a.w;
    }
    *(float4*)&dout[(size_t)m * HD + c * 4] = s;
}

// ---------------------------------------------------------------------------
// Split-KV flash attention + fused K/V cache copy (f32x2 inner GEMMs).
// Grid (NSPLIT, 256 bh), 256 threads, 62.4KB dyn smem, 3 blocks/SM.
// ---------------------------------------------------------------------------
__global__ __launch_bounds__(256, 3) void flash_k(
    const float* __restrict__ kcache, const float* __restrict__ vcache,
    const int* __restrict__ mask, float* __restrict__ dout)
{
    extern __shared__ float sm[];
    float4* kvs4 = (float4*)sm;            // 96*32 = 3072 f4
    float4* qs4  = (float4*)(sm + 12288);  // 512 f4
    float*  ps   = sm + 14336;             // [16][100]
    float*  m_s  = sm + 15936;
    float*  l_s  = sm + 15952;
    const ulonglong2* kvsu = (const ulonglong2*)kvs4;
    const ulonglong2* qsu  = (const ulonglong2*)qs4;

    int split = blockIdx.x;
    int bh    = blockIdx.y;
    int b     = bh >> 5;
    int kv0   = split * CHUNK;
    int rows  = min(CHUNK, KVL - kv0);
    int t     = threadIdx.x;
    int lane  = t & 31;
    int wid   = t >> 5;   // 0..7

    const float4* qsrc = (const float4*)(g_q + (size_t)bh * SS * DD);
#pragma unroll
    for (int i = t; i < 512; i += 256) qs4[i] = qsrc[i];

    float* kout = dout + K_OFF + (size_t)bh * KVL * DD;
    for (int i = t; i < rows * 32; i += 256) {
        int r = i >> 5, c = i & 31;
        int kv = kv0 + r;
        const float4* src = (kv < PASTL)
            ? (const float4*)(kcache + ((size_t)bh * PASTL + kv) * DD)
            : (const float4*)(kout + (size_t)kv * DD);
        float4 v = src[c];
        kvs4[r * 32 + (c ^ (r & 7))] = v;
        if (kv < PASTL) ((float4*)(kout + (size_t)kv * DD))[c] = v;
    }
    for (int i = rows * 32 + t; i < CHUNK * 32; i += 256) {
        int r = i >> 5, c = i & 31;
        kvs4[r * 32 + (c ^ (r & 7))] = make_float4(0.f, 0.f, 0.f, 0.f);
    }
    __syncthreads();

    // ---- S = Q K^T : warp = 2 s rows, lane = kv col (+32j, j<3) ----
    int kvc = lane;
    int s0  = wid * 2;
    {
        unsigned long long acc2[2][3];
#pragma unroll
        for (int i = 0; i < 2; i++)
#pragma unroll
            for (int j = 0; j < 3; j++) acc2[i][j] = 0ULL;

#pragma unroll 4
        for (int k4 = 0; k4 < 32; k4++) {
            ulonglong2 kf[3];
#pragma unroll
            for (int j = 0; j < 3; j++) {
                int kv = kvc + 32 * j;
                kf[j] = kvsu[kv * 32 + (k4 ^ (kv & 7))];
            }
#pragma unroll
            for (int i = 0; i < 2; i++) {
                ulonglong2 q = qsu[(s0 + i) * 32 + k4];
#pragma unroll
                for (int j = 0; j < 3; j++) {
                    fma2(acc2[i][j], q.x, kf[j].x);
                    fma2(acc2[i][j], q.y, kf[j].y);
                }
            }
        }

        const float scale = 0.08838834764831845f;  // 1/sqrt(128)
#pragma unroll
        for (int i = 0; i < 2; i++) {
            int s = s0 + i;
#pragma unroll
            for (int j = 0; j < 3; j++) {
                int kv  = kvc + 32 * j;
                int kvg = kv0 + kv;
                float lg;
                if (kvg >= KVL) lg = -1e30f;
                else {
                    float2 f = unpk(acc2[i][j]);
                    lg = (f.x + f.y) * scale;
                    if (mask[(size_t)(b * SS + s) * KVL + kvg] == 0) lg = -1e30f;
                }
                ps[s * 100 + kv] = lg;
            }
        }
    }
    __syncthreads();

    // ---- row max (8 warps x 2 rows) ----
#pragma unroll
    for (int rr = 0; rr < 2; rr++) {
        int row = wid * 2 + rr;
        float v = fmaxf(fmaxf(ps[row * 100 + lane], ps[row * 100 + lane + 32]),
                        ps[row * 100 + lane + 64]);
#pragma unroll
        for (int o = 16; o > 0; o >>= 1) v = fmaxf(v, __shfl_xor_sync(0xffffffffu, v, o));
        if (lane == 0) m_s[row] = v;
    }
    __syncthreads();

    // ---- exp pass + V tile load + fused V copy ----
#pragma unroll
    for (int i = 0; i < 2; i++) {
        float m = m_s[s0 + i];
#pragma unroll
        for (int j = 0; j < 3; j++) {
            float* p = &ps[(s0 + i) * 100 + kvc + 32 * j];
            *p = __expf(*p - m);
        }
    }
    float* vout = dout + V_OFF + (size_t)bh * KVL * DD;
    for (int i = t; i < rows * 32; i += 256) {
        int r = i >> 5, c = i & 31;
        int kv = kv0 + r;
        const float4* src = (kv < PASTL)
            ? (const float4*)(vcache + ((size_t)bh * PASTL + kv) * DD)
            : (const float4*)(vout + (size_t)kv * DD);
        float4 v = src[c];
        kvs4[r * 32 + (c ^ (r & 7))] = v;
        if (kv < PASTL) ((float4*)(vout + (size_t)kv * DD))[c] = v;
    }
    for (int i = rows * 32 + t; i < CHUNK * 32; i += 256) {
        int r = i >> 5, c = i & 31;
        kvs4[r * 32 + (c ^ (r & 7))] = make_float4(0.f, 0.f, 0.f, 0.f);
    }
    __syncthreads();

    // ---- row sum ----
#pragma unroll
    for (int rr = 0; rr < 2; rr++) {
        int row = wid * 2 + rr;
        float v = ps[row * 100 + lane] + ps[row * 100 + lane + 32]
                + ps[row * 100 + lane + 64];
#pragma unroll
        for (int o = 16; o > 0; o >>= 1) v += __shfl_xor_sync(0xffffffffu, v, o);
        if (lane == 0) l_s[row] = v;
    }
    __syncthreads();

    // ---- O_partial = P V : warp = 2 s rows, lane = 4 d ----
    {
        int dg = lane;
        unsigned long long o2[2][2];
#pragma unroll
        for (int i = 0; i < 2; i++) { o2[i][0] = 0ULL; o2[i][1] = 0ULL; }

        const float4* ps4 = (const float4*)ps;  // row stride 25 f4
#pragma unroll 4
        for (int kv4 = 0; kv4 < 24; kv4++) {
            ulonglong2 vv[4];
#pragma unroll
            for (int j = 0; j < 4; j++) {
                int kv = kv4 * 4 + j;
                vv[j] = kvsu[kv * 32 + (dg ^ (kv & 7))];
            }
#pragma unroll
            for (int i = 0; i < 2; i++) {
                float4 p4 = ps4[(s0 + i) * 25 + kv4];
                unsigned long long pd;
                pd = dup2(p4.x); fma2(o2[i][0], pd, vv[0].x); fma2(o2[i][1], pd, vv[0].y);
                pd = dup2(p4.y); fma2(o2[i][0], pd, vv[1].x); fma2(o2[i][1], pd, vv[1].y);
                pd = dup2(p4.z); fma2(o2[i][0], pd, vv[2].x); fma2(o2[i][1], pd, vv[2].y);
                pd = dup2(p4.w); fma2(o2[i][0], pd, vv[3].x); fma2(o2[i][1], pd, vv[3].y);
            }
        }

        size_t base = ((size_t)split * 256 + bh) * (SS * DD);
#pragma unroll
        for (int i = 0; i < 2; i++) {
            int s = s0 + i;
            float2 l0 = unpk(o2[i][0]);
            float2 l1 = unpk(o2[i][1]);
            ((float4*)(g_pacc + base + (size_t)s * DD))[dg] =
                make_float4(l0.x, l0.y, l1.x, l1.y);
        }
    }
    if (t < 16) {
        size_t idx = ((size_t)split * 256 + bh) * SS + t;
        g_pm[idx] = m_s[t];
        g_pl[idx] = l_s[t];
    }
}

// ---------------------------------------------------------------------------
// Combine split partials -> g_attn. Grid 256 (bh), 512 threads (s, dg).
// ---------------------------------------------------------------------------
__global__ __launch_bounds__(512) void combine_k()
{
    int bh = blockIdx.x;
    int t  = threadIdx.x;
    int dg = t & 31, s = t >> 5;
    int b = bh >> 5, h = bh & 31;

    float M = -3.4e38f;
#pragma unroll 11
    for (int sp = 0; sp < NSPLIT; sp++)
        M = fmaxf(M, g_pm[((size_t)sp * 256 + bh) * SS + s]);
    float lsum = 0.f;
    float4 o = make_float4(0.f, 0.f, 0.f, 0.f);
#pragma unroll 11
    for (int sp = 0; sp < NSPLIT; sp++) {
        size_t idx = (size_t)sp * 256 + bh;
        float f = __expf(g_pm[idx * SS + s] - M);
        lsum += f * g_pl[idx * SS + s];
        float4 a = ((const float4*)(g_pacc + idx * (SS * DD) + (size_t)s * DD))[dg];
        o.x += f * a.x; o.y += f * a.y; o.z += f * a.z; o.w += f * a.w;
    }
    float inv = 1.0f / lsum;
    o.x *= inv; o.y *= inv; o.z *= inv; o.w *= inv;
    ((float4*)(g_attn + ((size_t)(b * SS + s)) * HD + h * DD))[dg] = o;
}

// ---------------------------------------------------------------------------
extern "C" void kernel_launch(void* const* d_in, const int* in_sizes, int n_in,
                              void* d_out, int out_size)
{
    const float* hidden = (const float*)d_in[0];
    const int*   mask   = (const int*)d_in[1];
    const float* kcache = (const float*)d_in[2];
    const float* vcache = (const float*)d_in[3];
    const float* Wq     = (const float*)d_in[4];
    const float* Wk     = (const float*)d_in[5];
    const float* Wv     = (const float*)d_in[6];
    const float* Wo     = (const float*)d_in[7];
    float* out = (float*)d_out;

    const int FLASH_SMEM = 15968 * 4;                        // 63872 B
    // staging 24576 + bf16 (128+64)*80*2 = 30720 + 1024 align = 56320 B
    const int SMG = 1024 + (128 * 32 * 4 + 64 * 32 * 4) + 2 * 128 * 80 + 2 * 64 * 80;
    cudaFuncSetAttribute(flash_k, cudaFuncAttributeMaxDynamicSharedMemorySize,
                         FLASH_SMEM);
    cudaFuncSetAttribute((gemm_mma<KS_QKV>),
                         cudaFuncAttributeMaxDynamicSharedMemorySize, SMG);
    cudaFuncSetAttribute((gemm_mma<KS_O>),
                         cudaFuncAttributeMaxDynamicSharedMemorySize, SMG);

    // 1. QKV projections, NT=64, split-K=2 (384 CTAs, 3/SM)
    gemm_mma<KS_QKV><<<dim3(192, KS_QKV), 256, SMG>>>(
        hidden, Wq, Wk, Wv, 12288, -1);
    // 2+3. Reduce + route, two half-launches (flash becomes launch #4)
    reduce_qkv_k<<<768, 256>>>(out, 0);
    reduce_qkv_k<<<768, 256>>>(out, 196608);
    // 4. Split-KV flash attention + fused K/V cache copies (profiled slot)
    flash_k<<<dim3(NSPLIT, 256), 256, FLASH_SMEM>>>(kcache, vcache, mask, out);
    // 5. Combine flash partials
    combine_k<<<256, 512>>>();
    // 6. Output projection, NT=64, split-K=6 (384 CTAs, 3/SM)
    gemm_mma<KS_O><<<dim3(64, KS_O), 256, SMG>>>(
        nullptr, Wo, Wo, Wo, 4096, 3);
    reduce_o_k<<<512, 256>>>(out);
}

// round 13
// speedup vs baseline: 1.0676x; 1.0676x over previous
#include <cuda_runtime.h>
#include <cuda_bf16.h>
#include <math.h>
#include <stdint.h>

#define BB   8
#define SS   16
#define IND  4096
#define HH   32
#define DD   128
#define PASTL 4096
#define KVL  4112
#define MM   128      /* B*S */
#define HD   4096     /* H*D */
#define CHUNK 96
#define NSPLIT 43     /* ceil(4112/96) */
#define KCHUNK 32
#define NCH  (IND / KCHUNK)   /* 128 */
#define KS_QKV 3
#define KS_O   4

static const size_t K_OFF    = (size_t)MM * IND;                 // 524288
static const size_t KV_ELEMS = (size_t)BB * HH * KVL * DD;       // 134742016
static const size_t V_OFF    = K_OFF + KV_ELEMS;

// Scratch (device globals: no allocation allowed)
__device__ float g_q[MM * HD];                  // [bh][s][d]
__device__ float g_attn[MM * HD];               // [m][h*128+d]
__device__ float g_part[(size_t)KS_O * MM * 3 * HD];      // split-K partials
__device__ float g_pacc[(size_t)NSPLIT * 256 * SS * DD];  // flash partial O
__device__ float g_pm[(size_t)NSPLIT * 256 * SS];
__device__ float g_pl[(size_t)NSPLIT * 256 * SS];

// ---------------- helpers ----------------
__device__ __forceinline__ uint32_t smem_u32(const void* p) {
    uint32_t a;
    asm("{ .reg .u64 t; cvta.to.shared.u64 t, %1; cvt.u32.u64 %0, t; }"
        : "=r"(a) : "l"(p));
    return a;
}
__device__ __forceinline__ void ldsm4(uint32_t* r, uint32_t addr) {
    asm volatile("ldmatrix.sync.aligned.m8n8.x4.shared.b16 {%0,%1,%2,%3}, [%4];"
        : "=r"(r[0]), "=r"(r[1]), "=r"(r[2]), "=r"(r[3]) : "r"(addr));
}
__device__ __forceinline__ void mma_bf16(float* d, const uint32_t* a,
                                         const uint32_t* b) {
    asm volatile(
        "mma.sync.aligned.m16n8k16.row.col.f32.bf16.bf16.f32 "
        "{%0,%1,%2,%3}, {%4,%5,%6,%7}, {%8,%9}, {%0,%1,%2,%3};"
        : "+f"(d[0]), "+f"(d[1]), "+f"(d[2]), "+f"(d[3])
        : "r"(a[0]), "r"(a[1]), "r"(a[2]), "r"(a[3]), "r"(b[0]), "r"(b[1]));
}
__device__ __forceinline__ void cpa16(uint32_t dst, const void* src) {
    asm volatile("cp.async.cg.shared.global [%0], [%1], 16;"
                 :: "r"(dst), "l"(src) : "memory");
}

// f32x2 helpers for flash kernel
__device__ __forceinline__ void fma2(unsigned long long& acc,
                                     unsigned long long a, unsigned long long b)
{
    asm("fma.rn.f32x2 %0, %1, %2, %0;" : "+l"(acc) : "l"(a), "l"(b));
}
__device__ __forceinline__ unsigned long long dup2(float x)
{
    unsigned long long r;
    unsigned int u = __float_as_uint(x);
    asm("mov.b64 %0, {%1, %1};" : "=l"(r) : "r"(u));
    return r;
}
__device__ __forceinline__ float2 unpk(unsigned long long v)
{
    unsigned int lo, hi;
    asm("mov.b64 {%0, %1}, %2;" : "=r"(lo), "=r"(hi) : "l"(v));
    return make_float2(__uint_as_float(lo), __uint_as_float(hi));
}

// Convert float4 -> bf16 hi/lo pairs, store (8B each) into 80B-stride rows.
__device__ __forceinline__ void cvt_store80(uint32_t hiBase, uint32_t loBase,
                                            int r, int c4, float4 v) {
    uint32_t h0, h1;
    asm("cvt.rn.bf16x2.f32 %0, %1, %2;" : "=r"(h0) : "f"(v.y), "f"(v.x));
    asm("cvt.rn.bf16x2.f32 %0, %1, %2;" : "=r"(h1) : "f"(v.w), "f"(v.z));
    float hx = __uint_as_float(h0 << 16), hy = __uint_as_float(h0 & 0xFFFF0000u);
    float hz = __uint_as_float(h1 << 16), hw = __uint_as_float(h1 & 0xFFFF0000u);
    float lx = v.x - hx, ly = v.y - hy, lz = v.z - hz, lw = v.w - hw;
    uint32_t l0, l1;
    asm("cvt.rn.bf16x2.f32 %0, %1, %2;" : "=r"(l0) : "f"(ly), "f"(lx));
    asm("cvt.rn.bf16x2.f32 %0, %1, %2;" : "=r"(l1) : "f"(lw), "f"(lz));
    uint32_t off = (uint32_t)(r * 80 + (c4 >> 1) * 16 + (c4 & 1) * 8);
    asm volatile("st.shared.v2.b32 [%0], {%1,%2};" :: "r"(hiBase + off), "r"(h0), "r"(h1));
    asm volatile("st.shared.v2.b32 [%0], {%1,%2};" :: "r"(loBase + off), "r"(l0), "r"(l1));
}

// ---------------------------------------------------------------------------
// bf16x3 MMA GEMM, split-K, cp.async double-staged pipeline (round-11 config).
// Y[m,n] = sum_k A[m,k] * W[n,k]. M=128, N-tile NT. KCHUNK=32.
// 256 threads = 8 warps (2m x 4n). Grid (ntiles, KS). Partials -> g_part.
// ---------------------------------------------------------------------------
template<int NT, int KS>
__global__ __launch_bounds__(256, 2) void gemm_mma(
    const float* __restrict__ A,
    const float* __restrict__ W0, const float* __restrict__ W1,
    const float* __restrict__ W2,
    int NTOT, int mode)
{
    constexpr int WN  = NT / 4;          // n per warp
    constexpr int NA  = WN / 8;          // n-atoms per warp (even)
    constexpr int NWJ = NT / 32;         // W row-groups per thread
    constexpr int ASTG = 128 * 32 * 4;   // fp32 staging, A chunk (16KB)
    constexpr int WSTG = NT * 32 * 4;    // fp32 staging, W chunk
    constexpr int STG  = ASTG + WSTG;

    extern __shared__ char dsm[];
    uint32_t dbase = (smem_u32(dsm) + 1023) & ~1023u;
    uint32_t stg = dbase;                  // 2 * STG raw fp32 staging
    uint32_t aHi = dbase + 2 * STG;        // bf16 buffers (single)
    uint32_t aLo = aHi + 128 * 80;
    uint32_t wHi = aLo + 128 * 80;
    uint32_t wLo = wHi + NT * 80;

    int t = threadIdx.x, wid = t >> 5, lane = t & 31;
    const int nperz = HD / NT;
    int tile  = blockIdx.x;
    int split = blockIdx.y;
    int z  = (mode < 0) ? (tile / nperz) : 0;
    int n0 = (mode < 0) ? (tile % nperz) * NT : tile * NT;
    const float* Ap = (mode == 3) ? g_attn : A;
    const float* W  = (z == 0) ? W0 : (z == 1) ? W1 : W2;

    int c_beg = (split * NCH) / KS;
    int c_end = ((split + 1) * NCH) / KS;

    int warp_m = wid & 1, warp_n = wid >> 1;

    float acc[4][NA][4];
#pragma unroll
    for (int i = 0; i < 4; i++)
#pragma unroll
        for (int j = 0; j < NA; j++)
#pragma unroll
            for (int q = 0; q < 4; q++) acc[i][j][q] = 0.f;

    int c4 = t & 7, r0 = t >> 3;
    int a_rowin = lane & 15, a_kb = lane >> 4;
    int b_sub = lane >> 3, b_rowin = lane & 7;
    int b_kb = b_sub & 1, b_half = (b_sub >> 1) & 1;

    auto issue_chunk = [&](int ch) {
        if (ch < c_end) {
            uint32_t sb = stg + (uint32_t)(((ch - c_beg) & 1) * STG);
            int k0 = ch * KCHUNK;
#pragma unroll
            for (int j = 0; j < 4; j++)
                cpa16(sb + (uint32_t)((r0 + 32 * j) * 128 + c4 * 16),
                      Ap + (size_t)(r0 + 32 * j) * IND + k0 + c4 * 4);
#pragma unroll
            for (int j = 0; j < NWJ; j++)
                cpa16(sb + ASTG + (uint32_t)((r0 + 32 * j) * 128 + c4 * 16),
                      W + (size_t)(n0 + r0 + 32 * j) * IND + k0 + c4 * 4);
        }
        asm volatile("cp.async.commit_group;" ::: "memory");
    };

    issue_chunk(c_beg);
    issue_chunk(c_beg + 1);

    for (int ch = c_beg; ch < c_end; ch++) {
        asm volatile("cp.async.wait_group 1;" ::: "memory");
        __syncthreads();

        uint32_t sb = stg + (uint32_t)(((ch - c_beg) & 1) * STG);
#pragma unroll
        for (int j = 0; j < 4; j++) {
            float4 v;
            uint32_t sa = sb + (uint32_t)((r0 + 32 * j) * 128 + c4 * 16);
            asm volatile("ld.shared.v4.f32 {%0,%1,%2,%3}, [%4];"
                : "=f"(v.x), "=f"(v.y), "=f"(v.z), "=f"(v.w) : "r"(sa));
            cvt_store80(aHi, aLo, r0 + 32 * j, c4, v);
        }
#pragma unroll
        for (int j = 0; j < NWJ; j++) {
            float4 v;
            uint32_t sa = sb + ASTG + (uint32_t)((r0 + 32 * j) * 128 + c4 * 16);
            asm volatile("ld.shared.v4.f32 {%0,%1,%2,%3}, [%4];"
                : "=f"(v.x), "=f"(v.y), "=f"(v.z), "=f"(v.w) : "r"(sa));
            cvt_store80(wHi, wLo, r0 + 32 * j, c4, v);
        }
        __syncthreads();

        issue_chunk(ch + 2);

#pragma unroll
        for (int ks = 0; ks < 2; ks++) {
            uint32_t bh[NA][2], bl[NA][2];
#pragma unroll
            for (int p = 0; p < NA / 2; p++) {
                int row = warp_n * WN + p * 16 + b_half * 8 + b_rowin;
                uint32_t o = (uint32_t)(row * 80 + (ks * 2 + b_kb) * 16);
                uint32_t r4[4];
                ldsm4(r4, wHi + o);
                bh[2 * p][0] = r4[0]; bh[2 * p][1] = r4[1];
                bh[2 * p + 1][0] = r4[2]; bh[2 * p + 1][1] = r4[3];
                ldsm4(r4, wLo + o);
                bl[2 * p][0] = r4[0]; bl[2 * p][1] = r4[1];
                bl[2 * p + 1][0] = r4[2]; bl[2 * p + 1][1] = r4[3];
            }
#pragma unroll
            for (int i = 0; i < 4; i++) {
                uint32_t ah[4], al[4];
                int row = warp_m * 64 + i * 16 + a_rowin;
                uint32_t o = (uint32_t)(row * 80 + (ks * 2 + a_kb) * 16);
                ldsm4(ah, aHi + o);
                ldsm4(al, aLo + o);
#pragma unroll
                for (int j = 0; j < NA; j++) {
                    mma_bf16(acc[i][j], ah, bh[j]);
                    mma_bf16(acc[i][j], ah, bl[j]);
                    mma_bf16(acc[i][j], al, bh[j]);
                }
            }
        }
    }

    int g = lane >> 2, tq = lane & 3;
#pragma unroll
    for (int i = 0; i < 4; i++) {
#pragma unroll
        for (int j = 0; j < NA; j++) {
            int col = z * 4096 + n0 + warp_n * WN + j * 8 + tq * 2;
#pragma unroll
            for (int half = 0; half < 2; half++) {
                int m = warp_m * 64 + i * 16 + g + half * 8;
                *(float2*)&g_part[(size_t)(split * MM + m) * NTOT + col] =
                    make_float2(acc[i][j][2 * half], acc[i][j][2 * half + 1]);
            }
        }
    }
}

// ---------------------------------------------------------------------------
// Reduce QKV split-K partials (KS_QKV) and route. 393216 float4s total,
// two half-launches so flash stays launch #4 for ncu.
// ---------------------------------------------------------------------------
__global__ __launch_bounds__(256) void reduce_qkv_k(float* __restrict__ dout,
                                                    int base)
{
    int i = base + blockIdx.x * 256 + threadIdx.x;  // float4 index
    int m = i / 3072, c = i - m * 3072;
    const float4* p = (const float4*)g_part;
    float4 s = p[(size_t)m * 3072 + c];
#pragma unroll
    for (int sp = 1; sp < KS_QKV; sp++) {
        float4 a = p[(size_t)(sp * MM + m) * 3072 + c];
        s.x += a.x; s.y += a.y; s.z += a.z; s.w += a.w;
    }
    int n  = c * 4;
    int z  = n >> 12, nl = n & 4095;
    int h  = nl >> 7, dd = nl & 127;
    int b  = m >> 4, sq = m & 15;
    if (z == 0) {
        *(float4*)&g_q[((size_t)(b * HH + h) * SS + sq) * DD + dd] = s;
    } else {
        size_t off = (z == 1) ? K_OFF : V_OFF;
        *(float4*)&dout[off + ((size_t)(b * HH + h) * KVL + PASTL + sq) * DD + dd] = s;
    }
}

// Reduce O-proj split-K partials (KS_O). 131072 float4s.
__global__ __launch_bounds__(256) void reduce_o_k(float* __restrict__ dout)
{
    int i = blockIdx.x * 256 + threadIdx.x;
    int m = i / 1024, c = i - m * 1024;
    const float4* p = (const float4*)g_part;
    float4 s = p[(size_t)m * 1024 + c];
#pragma unroll
    for (int sp = 1; sp < KS_O; sp++) {
        float4 a = p[(size_t)(sp * MM + m) * 1024 + c];
        s.x += a.x; s.y += a.y; s.z += a.z; s.w += a.w;
    }
    *(float4*)&dout[(size_t)m * HD + c * 4] = s;
}

// ---------------------------------------------------------------------------
// Split-KV flash attention + fused K/V cache copy, reduction-split blocking.
// Grid (NSPLIT, 256 bh), 256 threads, 70.3KB dyn smem, 3 blocks/SM.
// QK^T: warp = (4 s-rows, d-half);  PV: warp = (4 s-rows, kv-half).
// Halves the per-CTA LDS traffic vs full-tile-per-warp.
// ---------------------------------------------------------------------------
__global__ __launch_bounds__(256, 3) void flash_k(
    const float* __restrict__ kcache, const float* __restrict__ vcache,
    const int* __restrict__ mask, float* __restrict__ dout)
{
    extern __shared__ float sm[];
    float4* kvs4 = (float4*)sm;            // 96*32 = 3072 f4
    float4* qs4  = (float4*)(sm + 12288);  // 512 f4 (reused as obuf in PV)
    float*  psA  = sm + 14336;             // [16][100]
    float*  psB  = sm + 15936;             // [16][100]
    float*  m_s  = sm + 17536;
    float*  l_s  = sm + 17552;
    const ulonglong2* kvsu = (const ulonglong2*)kvs4;
    const ulonglong2* qsu  = (const ulonglong2*)qs4;

    int split = blockIdx.x;
    int bh    = blockIdx.y;
    int b     = bh >> 5;
    int kv0   = split * CHUNK;
    int rows  = min(CHUNK, KVL - kv0);
    int t     = threadIdx.x;
    int lane  = t & 31;
    int wid   = t >> 5;     // 0..7
    int sgrp  = wid & 3;    // 4 s-rows group
    int rep   = wid >> 2;   // reduction-split replica (0/1)
    int s0    = sgrp * 4;

    // ---- Q load + K tile load (swizzled) + fused K copy ----
    const float4* qsrc = (const float4*)(g_q + (size_t)bh * SS * DD);
#pragma unroll
    for (int i = t; i < 512; i += 256) qs4[i] = qsrc[i];

    float* kout = dout + K_OFF + (size_t)bh * KVL * DD;
    for (int i = t; i < rows * 32; i += 256) {
        int r = i >> 5, c = i & 31;
        int kv = kv0 + r;
        const float4* src = (kv < PASTL)
            ? (const float4*)(kcache + ((size_t)bh * PASTL + kv) * DD)
            : (const float4*)(kout + (size_t)kv * DD);
        float4 v = src[c];
        kvs4[r * 32 + (c ^ (r & 7))] = v;
        if (kv < PASTL) ((float4*)(kout + (size_t)kv * DD))[c] = v;
    }
    for (int i = rows * 32 + t; i < CHUNK * 32; i += 256) {
        int r = i >> 5, c = i & 31;
        kvs4[r * 32 + (c ^ (r & 7))] = make_float4(0.f, 0.f, 0.f, 0.f);
    }
    __syncthreads();

    // ---- S = Q K^T, d-split: warp covers 4 s rows, half of k-range ----
    {
        unsigned long long acc2[4][3];
#pragma unroll
        for (int i = 0; i < 4; i++)
#pragma unroll
            for (int j = 0; j < 3; j++) acc2[i][j] = 0ULL;

        int k4b = rep * 16;
#pragma unroll
        for (int j = 0; j < 3; j++) {
            int kv = lane + 32 * j;
            const ulonglong2* krow = kvsu + kv * 32;
            int kmask = kv & 7;
#pragma unroll 4
            for (int k4i = 0; k4i < 16; k4i++) {
                int k4 = k4b + k4i;
                ulonglong2 kf = krow[k4 ^ kmask];
#pragma unroll
                for (int i = 0; i < 4; i++) {
                    ulonglong2 q = qsu[(s0 + i) * 32 + k4];
                    fma2(acc2[i][j], q.x, kf.x);
                    fma2(acc2[i][j], q.y, kf.y);
                }
            }
        }
        float* dst = rep ? psB : psA;
#pragma unroll
        for (int i = 0; i < 4; i++)
#pragma unroll
            for (int j = 0; j < 3; j++) {
                float2 f = unpk(acc2[i][j]);
                dst[(s0 + i) * 100 + lane + 32 * j] = f.x + f.y;
            }
    }
    __syncthreads();

    // ---- finalize (sum halves, scale, mask, rowmax) + V load + fused copy ----
    const float scale = 0.08838834764831845f;  // 1/sqrt(128)
#pragma unroll
    for (int rr = 0; rr < 2; rr++) {
        int row = wid * 2 + rr;
        float vmax = -3.4e38f;
#pragma unroll
        for (int j = 0; j < 3; j++) {
            int c = lane + 32 * j;
            int kvg = kv0 + c;
            float lg;
            if (kvg >= KVL) lg = -1e30f;
            else {
                lg = (psA[row * 100 + c] + psB[row * 100 + c]) * scale;
                if (mask[(size_t)(b * SS + row) * KVL + kvg] == 0) lg = -1e30f;
            }
            psA[row * 100 + c] = lg;
            vmax = fmaxf(vmax, lg);
        }
#pragma unroll
        for (int o = 16; o > 0; o >>= 1)
            vmax = fmaxf(vmax, __shfl_xor_sync(0xffffffffu, vmax, o));
        if (lane == 0) m_s[row] = vmax;
    }
    float* vout = dout + V_OFF + (size_t)bh * KVL * DD;
    for (int i = t; i < rows * 32; i += 256) {
        int r = i >> 5, c = i & 31;
        int kv = kv0 + r;
        const float4* src = (kv < PASTL)
            ? (const float4*)(vcache + ((size_t)bh * PASTL + kv) * DD)
            : (const float4*)(vout + (size_t)kv * DD);
        float4 v = src[c];
        kvs4[r * 32 + (c ^ (r & 7))] = v;
        if (kv < PASTL) ((float4*)(vout + (size_t)kv * DD))[c] = v;
    }
    for (int i = rows * 32 + t; i < CHUNK * 32; i += 256) {
        int r = i >> 5, c = i & 31;
        kvs4[r * 32 + (c ^ (r & 7))] = make_float4(0.f, 0.f, 0.f, 0.f);
    }
    __syncthreads();

    // ---- exp + row sum ----
#pragma unroll
    for (int rr = 0; rr < 2; rr++) {
        int row = wid * 2 + rr;
        float m = m_s[row];
        float sum = 0.f;
#pragma unroll
        for (int j = 0; j < 3; j++) {
            int c = lane + 32 * j;
            float e = __expf(psA[row * 100 + c] - m);
            psA[row * 100 + c] = e;
            sum += e;
        }
#pragma unroll
        for (int o = 16; o > 0; o >>= 1) sum += __shfl_xor_sync(0xffffffffu, sum, o);
        if (lane == 0) l_s[row] = sum;
    }
    __syncthreads();

    // ---- O_partial = P V, kv-split: warp = 4 s rows x kv-half; lane = 4 d ----
    {
        int dg = lane;
        unsigned long long o2[4][2];
#pragma unroll
        for (int i = 0; i < 4; i++) { o2[i][0] = 0ULL; o2[i][1] = 0ULL; }

        const float4* ps4 = (const float4*)psA;  // row stride 25 f4
#pragma unroll
        for (int j = 0; j < 4; j++) {
#pragma unroll 4
            for (int kv4 = 0; kv4 < 12; kv4++) {
                int kv = rep * 48 + kv4 * 4 + j;
                ulonglong2 vv = kvsu[kv * 32 + (dg ^ (kv & 7))];
#pragma unroll
                for (int i = 0; i < 4; i++) {
                    float p = psA[(s0 + i) * 100 + kv];
                    unsigned long long pd = dup2(p);
                    fma2(o2[i][0], pd, vv.x);
                    fma2(o2[i][1], pd, vv.y);
                }
            }
        }

        float4* obuf = qs4;  // Q dead; reuse as partial-O buffer [16][32] f4
        if (rep == 0) {
#pragma unroll
            for (int i = 0; i < 4; i++) {
                float2 l0 = unpk(o2[i][0]);
                float2 l1 = unpk(o2[i][1]);
                obuf[(s0 + i) * 32 + dg] = make_float4(l0.x, l0.y, l1.x, l1.y);
            }
        }
        __syncthreads();
        if (rep == 1) {
            size_t base = ((size_t)split * 256 + bh) * (SS * DD);
#pragma unroll
            for (int i = 0; i < 4; i++) {
                float2 l0 = unpk(o2[i][0]);
                float2 l1 = unpk(o2[i][1]);
                float4 a = obuf[(s0 + i) * 32 + dg];
                ((float4*)(g_pacc + base + (size_t)(s0 + i) * DD))[dg] =
                    make_float4(a.x + l0.x, a.y + l0.y, a.z + l1.x, a.w + l1.y);
            }
        }
    }
    if (t < 16) {
        size_t idx = ((size_t)split * 256 + bh) * SS + t;
        g_pm[idx] = m_s[t];
        g_pl[idx] = l_s[t];
    }
}

// ---------------------------------------------------------------------------
// Combine split partials -> g_attn. Grid 256 (bh), 512 threads (s, dg).
// ---------------------------------------------------------------------------
__global__ __launch_bounds__(512) void combine_k()
{
    int bh = blockIdx.x;
    int t  = threadIdx.x;
    int dg = t & 31, s = t >> 5;
    int b = bh >> 5, h = bh & 31;

    float M = -3.4e38f;
#pragma unroll 11
    for (int sp = 0; sp < NSPLIT; sp++)
        M = fmaxf(M, g_pm[((size_t)sp * 256 + bh) * SS + s]);
    float lsum = 0.f;
    float4 o = make_float4(0.f, 0.f, 0.f, 0.f);
#pragma unroll 11
    for (int sp = 0; sp < NSPLIT; sp++) {
        size_t idx = (size_t)sp * 256 + bh;
        float f = __expf(g_pm[idx * SS + s] - M);
        lsum += f * g_pl[idx * SS + s];
        float4 a = ((const float4*)(g_pacc + idx * (SS * DD) + (size_t)s * DD))[dg];
        o.x += f * a.x; o.y += f * a.y; o.z += f * a.z; o.w += f * a.w;
    }
    float inv = 1.0f / lsum;
    o.x *= inv; o.y *= inv; o.z *= inv; o.w *= inv;
    ((float4*)(g_attn + ((size_t)(b * SS + s)) * HD + h * DD))[dg] = o;
}

// ---------------------------------------------------------------------------
extern "C" void kernel_launch(void* const* d_in, const int* in_sizes, int n_in,
                              void* d_out, int out_size)
{
    const float* hidden = (const float*)d_in[0];
    const int*   mask   = (const int*)d_in[1];
    const float* kcache = (const float*)d_in[2];
    const float* vcache = (const float*)d_in[3];
    const float* Wq     = (const float*)d_in[4];
    const float* Wk     = (const float*)d_in[5];
    const float* Wv     = (const float*)d_in[6];
    const float* Wo     = (const float*)d_in[7];
    float* out = (float*)d_out;

    const int FLASH_SMEM = 17568 * 4;                            // 70272 B
    const int SM128 = 1024 + 2 * (128 * 32 * 4 + 128 * 32 * 4) + 4 * 128 * 80;
    const int SM64  = 1024 + 2 * (128 * 32 * 4 + 64 * 32 * 4)
                    + 2 * 128 * 80 + 2 * 64 * 80;
    cudaFuncSetAttribute(flash_k, cudaFuncAttributeMaxDynamicSharedMemorySize,
                         FLASH_SMEM);
    cudaFuncSetAttribute((gemm_mma<128, KS_QKV>),
                         cudaFuncAttributeMaxDynamicSharedMemorySize, SM128);
    cudaFuncSetAttribute((gemm_mma<64, KS_O>),
                         cudaFuncAttributeMaxDynamicSharedMemorySize, SM64);

    // 1. QKV projections (round-11 config: NT=128, split-K=3)
    gemm_mma<128, KS_QKV><<<dim3(96, KS_QKV), 256, SM128>>>(
        hidden, Wq, Wk, Wv, 12288, -1);
    // 2+3. Reduce + route in two half-launches (flash stays launch #4)
    reduce_qkv_k<<<768, 256>>>(out, 0);
    reduce_qkv_k<<<768, 256>>>(out, 196608);
    // 4. Split-KV flash attention (reduction-split blocking) + K/V copies
    flash_k<<<dim3(NSPLIT, 256), 256, FLASH_SMEM>>>(kcache, vcache, mask, out);
    // 5. Combine flash partials
    combine_k<<<256, 512>>>();
    // 6. Output projection (round-11 config: NT=64, split-K=4)
    gemm_mma<64, KS_O><<<dim3(64, KS_O), 256, SM64>>>(
        nullptr, Wo, Wo, Wo, 4096, 3);
    reduce_o_k<<<512, 256>>>(out);
}

// round 15
// speedup vs baseline: 1.2083x; 1.1318x over previous
#include <cuda_runtime.h>
#include <cuda_bf16.h>
#include <math.h>
#include <stdint.h>

#define BB   8
#define SS   16
#define IND  4096
#define HH   32
#define DD   128
#define PASTL 4096
#define KVL  4112
#define MM   128      /* B*S */
#define HD   4096     /* H*D */
#define CHUNK 96
#define NSPLIT 43     /* ceil(4112/96) */
#define KCHUNK 32
#define NCH  (IND / KCHUNK)   /* 128 */
#define KS_QKV 3
#define KS_O   4

static const size_t K_OFF    = (size_t)MM * IND;                 // 524288
static const size_t KV_ELEMS = (size_t)BB * HH * KVL * DD;       // 134742016
static const size_t V_OFF    = K_OFF + KV_ELEMS;

// Scratch (device globals: no allocation allowed)
__device__ float g_q[MM * HD];                  // [bh][s][d]
__device__ float g_attn[MM * HD];               // [m][h*128+d]
__device__ float g_part[(size_t)KS_O * MM * 3 * HD];      // split-K partials
__device__ float g_pacc[(size_t)NSPLIT * 256 * SS * DD];  // flash partial O
__device__ float g_pm[(size_t)NSPLIT * 256 * SS];
__device__ float g_pl[(size_t)NSPLIT * 256 * SS];

// ---------------- helpers ----------------
__device__ __forceinline__ uint32_t smem_u32(const void* p) {
    uint32_t a;
    asm("{ .reg .u64 t; cvta.to.shared.u64 t, %1; cvt.u32.u64 %0, t; }"
        : "=r"(a) : "l"(p));
    return a;
}
__device__ __forceinline__ void ldsm4(uint32_t* r, uint32_t addr) {
    asm volatile("ldmatrix.sync.aligned.m8n8.x4.shared.b16 {%0,%1,%2,%3}, [%4];"
        : "=r"(r[0]), "=r"(r[1]), "=r"(r[2]), "=r"(r[3]) : "r"(addr));
}
__device__ __forceinline__ void ldsm4t(uint32_t* r, uint32_t addr) {
    asm volatile("ldmatrix.sync.aligned.m8n8.x4.trans.shared.b16 {%0,%1,%2,%3}, [%4];"
        : "=r"(r[0]), "=r"(r[1]), "=r"(r[2]), "=r"(r[3]) : "r"(addr));
}
__device__ __forceinline__ void mma_bf16(float* d, const uint32_t* a,
                                         const uint32_t* b) {
    asm volatile(
        "mma.sync.aligned.m16n8k16.row.col.f32.bf16.bf16.f32 "
        "{%0,%1,%2,%3}, {%4,%5,%6,%7}, {%8,%9}, {%0,%1,%2,%3};"
        : "+f"(d[0]), "+f"(d[1]), "+f"(d[2]), "+f"(d[3])
        : "r"(a[0]), "r"(a[1]), "r"(a[2]), "r"(a[3]), "r"(b[0]), "r"(b[1]));
}
__device__ __forceinline__ void cpa16(uint32_t dst, const void* src) {
    asm volatile("cp.async.cg.shared.global [%0], [%1], 16;"
                 :: "r"(dst), "l"(src) : "memory");
}

// Convert float4 -> bf16 hi/lo pairs (8B each) at given row stride.
__device__ __forceinline__ void cvt_store_s(uint32_t hiBase, uint32_t loBase,
                                            uint32_t off, float4 v) {
    uint32_t h0, h1;
    asm("cvt.rn.bf16x2.f32 %0, %1, %2;" : "=r"(h0) : "f"(v.y), "f"(v.x));
    asm("cvt.rn.bf16x2.f32 %0, %1, %2;" : "=r"(h1) : "f"(v.w), "f"(v.z));
    float hx = __uint_as_float(h0 << 16), hy = __uint_as_float(h0 & 0xFFFF0000u);
    float hz = __uint_as_float(h1 << 16), hw = __uint_as_float(h1 & 0xFFFF0000u);
    float lx = v.x - hx, ly = v.y - hy, lz = v.z - hz, lw = v.w - hw;
    uint32_t l0, l1;
    asm("cvt.rn.bf16x2.f32 %0, %1, %2;" : "=r"(l0) : "f"(ly), "f"(lx));
    asm("cvt.rn.bf16x2.f32 %0, %1, %2;" : "=r"(l1) : "f"(lw), "f"(lz));
    asm volatile("st.shared.v2.b32 [%0], {%1,%2};" :: "r"(hiBase + off), "r"(h0), "r"(h1));
    asm volatile("st.shared.v2.b32 [%0], {%1,%2};" :: "r"(loBase + off), "r"(l0), "r"(l1));
}
__device__ __forceinline__ void cvt_store80(uint32_t hiBase, uint32_t loBase,
                                            int r, int c4, float4 v) {
    cvt_store_s(hiBase, loBase,
                (uint32_t)(r * 80 + (c4 >> 1) * 16 + (c4 & 1) * 8), v);
}

// ---------------------------------------------------------------------------
// bf16x3 MMA GEMM, split-K, cp.async double-staged pipeline (round-11 config).
// ---------------------------------------------------------------------------
template<int NT, int KS>
__global__ __launch_bounds__(256, 2) void gemm_mma(
    const float* __restrict__ A,
    const float* __restrict__ W0, const float* __restrict__ W1,
    const float* __restrict__ W2,
    int NTOT, int mode)
{
    constexpr int WN  = NT / 4;
    constexpr int NA  = WN / 8;
    constexpr int NWJ = NT / 32;
    constexpr int ASTG = 128 * 32 * 4;
    constexpr int WSTG = NT * 32 * 4;
    constexpr int STG  = ASTG + WSTG;

    extern __shared__ char dsm[];
    uint32_t dbase = (smem_u32(dsm) + 1023) & ~1023u;
    uint32_t stg = dbase;
    uint32_t aHi = dbase + 2 * STG;
    uint32_t aLo = aHi + 128 * 80;
    uint32_t wHi = aLo + 128 * 80;
    uint32_t wLo = wHi + NT * 80;

    int t = threadIdx.x, wid = t >> 5, lane = t & 31;
    const int nperz = HD / NT;
    int tile  = blockIdx.x;
    int split = blockIdx.y;
    int z  = (mode < 0) ? (tile / nperz) : 0;
    int n0 = (mode < 0) ? (tile % nperz) * NT : tile * NT;
    const float* Ap = (mode == 3) ? g_attn : A;
    const float* W  = (z == 0) ? W0 : (z == 1) ? W1 : W2;

    int c_beg = (split * NCH) / KS;
    int c_end = ((split + 1) * NCH) / KS;

    int warp_m = wid & 1, warp_n = wid >> 1;

    float acc[4][NA][4];
#pragma unroll
    for (int i = 0; i < 4; i++)
#pragma unroll
        for (int j = 0; j < NA; j++)
#pragma unroll
            for (int q = 0; q < 4; q++) acc[i][j][q] = 0.f;

    int c4 = t & 7, r0 = t >> 3;
    int a_rowin = lane & 15, a_kb = lane >> 4;
    int b_sub = lane >> 3, b_rowin = lane & 7;
    int b_kb = b_sub & 1, b_half = (b_sub >> 1) & 1;

    auto issue_chunk = [&](int ch) {
        if (ch < c_end) {
            uint32_t sb = stg + (uint32_t)(((ch - c_beg) & 1) * STG);
            int k0 = ch * KCHUNK;
#pragma unroll
            for (int j = 0; j < 4; j++)
                cpa16(sb + (uint32_t)((r0 + 32 * j) * 128 + c4 * 16),
                      Ap + (size_t)(r0 + 32 * j) * IND + k0 + c4 * 4);
#pragma unroll
            for (int j = 0; j < NWJ; j++)
                cpa16(sb + ASTG + (uint32_t)((r0 + 32 * j) * 128 + c4 * 16),
                      W + (size_t)(n0 + r0 + 32 * j) * IND + k0 + c4 * 4);
        }
        asm volatile("cp.async.commit_group;" ::: "memory");
    };

    issue_chunk(c_beg);
    issue_chunk(c_beg + 1);

    for (int ch = c_beg; ch < c_end; ch++) {
        asm volatile("cp.async.wait_group 1;" ::: "memory");
        __syncthreads();

        uint32_t sb = stg + (uint32_t)(((ch - c_beg) & 1) * STG);
#pragma unroll
        for (int j = 0; j < 4; j++) {
            float4 v;
            uint32_t sa = sb + (uint32_t)((r0 + 32 * j) * 128 + c4 * 16);
            asm volatile("ld.shared.v4.f32 {%0,%1,%2,%3}, [%4];"
                : "=f"(v.x), "=f"(v.y), "=f"(v.z), "=f"(v.w) : "r"(sa));
            cvt_store80(aHi, aLo, r0 + 32 * j, c4, v);
        }
#pragma unroll
        for (int j = 0; j < NWJ; j++) {
            float4 v;
            uint32_t sa = sb + ASTG + (uint32_t)((r0 + 32 * j) * 128 + c4 * 16);
            asm volatile("ld.shared.v4.f32 {%0,%1,%2,%3}, [%4];"
                : "=f"(v.x), "=f"(v.y), "=f"(v.z), "=f"(v.w) : "r"(sa));
            cvt_store80(wHi, wLo, r0 + 32 * j, c4, v);
        }
        __syncthreads();

        issue_chunk(ch + 2);

#pragma unroll
        for (int ks = 0; ks < 2; ks++) {
            uint32_t bh[NA][2], bl[NA][2];
#pragma unroll
            for (int p = 0; p < NA / 2; p++) {
                int row = warp_n * WN + p * 16 + b_half * 8 + b_rowin;
                uint32_t o = (uint32_t)(row * 80 + (ks * 2 + b_kb) * 16);
                uint32_t r4[4];
                ldsm4(r4, wHi + o);
                bh[2 * p][0] = r4[0]; bh[2 * p][1] = r4[1];
                bh[2 * p + 1][0] = r4[2]; bh[2 * p + 1][1] = r4[3];
                ldsm4(r4, wLo + o);
                bl[2 * p][0] = r4[0]; bl[2 * p][1] = r4[1];
                bl[2 * p + 1][0] = r4[2]; bl[2 * p + 1][1] = r4[3];
            }
#pragma unroll
            for (int i = 0; i < 4; i++) {
                uint32_t ah[4], al[4];
                int row = warp_m * 64 + i * 16 + a_rowin;
                uint32_t o = (uint32_t)(row * 80 + (ks * 2 + a_kb) * 16);
                ldsm4(ah, aHi + o);
                ldsm4(al, aLo + o);
#pragma unroll
                for (int j = 0; j < NA; j++) {
                    mma_bf16(acc[i][j], ah, bh[j]);
                    mma_bf16(acc[i][j], ah, bl[j]);
                    mma_bf16(acc[i][j], al, bh[j]);
                }
            }
        }
    }

    int g = lane >> 2, tq = lane & 3;
#pragma unroll
    for (int i = 0; i < 4; i++) {
#pragma unroll
        for (int j = 0; j < NA; j++) {
            int col = z * 4096 + n0 + warp_n * WN + j * 8 + tq * 2;
#pragma unroll
            for (int half = 0; half < 2; half++) {
                int m = warp_m * 64 + i * 16 + g + half * 8;
                *(float2*)&g_part[(size_t)(split * MM + m) * NTOT + col] =
                    make_float2(acc[i][j][2 * half], acc[i][j][2 * half + 1]);
            }
        }
    }
}

// ---------------------------------------------------------------------------
// Reduce QKV split-K partials; two half-launches keep flash at launch #4.
// ---------------------------------------------------------------------------
__global__ __launch_bounds__(256) void reduce_qkv_k(float* __restrict__ dout,
                                                    int base)
{
    int i = base + blockIdx.x * 256 + threadIdx.x;
    int m = i / 3072, c = i - m * 3072;
    const float4* p = (const float4*)g_part;
    float4 s = p[(size_t)m * 3072 + c];
#pragma unroll
    for (int sp = 1; sp < KS_QKV; sp++) {
        float4 a = p[(size_t)(sp * MM + m) * 3072 + c];
        s.x += a.x; s.y += a.y; s.z += a.z; s.w += a.w;
    }
    int n  = c * 4;
    int z  = n >> 12, nl = n & 4095;
    int h  = nl >> 7, dd = nl & 127;
    int b  = m >> 4, sq = m & 15;
    if (z == 0) {
        *(float4*)&g_q[((size_t)(b * HH + h) * SS + sq) * DD + dd] = s;
    } else {
        size_t off = (z == 1) ? K_OFF : V_OFF;
        *(float4*)&dout[off + ((size_t)(b * HH + h) * KVL + PASTL + sq) * DD + dd] = s;
    }
}

__global__ __launch_bounds__(256) void reduce_o_k(float* __restrict__ dout)
{
    int i = blockIdx.x * 256 + threadIdx.x;
    int m = i / 1024, c = i - m * 1024;
    const float4* p = (const float4*)g_part;
    float4 s = p[(size_t)m * 1024 + c];
#pragma unroll
    for (int sp = 1; sp < KS_O; sp++) {
        float4 a = p[(size_t)(sp * MM + m) * 1024 + c];
        s.x += a.x; s.y += a.y; s.z += a.z; s.w += a.w;
    }
    *(float4*)&dout[(size_t)m * HD + c * 4] = s;
}

// ---------------------------------------------------------------------------
// Split-KV flash attention on tensor cores (bf16x3) + fused K/V cache copy.
// Grid (NSPLIT, 256 bh), 256 threads, 74.1KB dyn smem, 3 blocks/SM.
// S: warps (3-natom group x k-half), partials psA/psB. PV: (4-datom x kv-half),
// V consumed via ldmatrix.trans. P converted to bf16 hi/lo post-softmax.
// ---------------------------------------------------------------------------
#define F_KHI 0u
#define F_KLO 26112u
#define F_QHI 52224u
#define F_QLO 56576u
#define F_PSA 60928u
#define F_PHI 67328u
#define F_PLO 70656u
#define F_MS  73984u
#define F_LS  74048u
__global__ __launch_bounds__(256, 3) void flash_k(
    const float* __restrict__ kcache, const float* __restrict__ vcache,
    const int* __restrict__ mask, float* __restrict__ dout)
{
    extern __shared__ char smc[];
    uint32_t sb = smem_u32(smc);
    float* psA = (float*)(smc + F_PSA);    // [16][100] fp32 (6400 B)
    float* psB = (float*)(smc + F_PHI);    // aliases P-bf16 region pre-softmax
    float* m_s = (float*)(smc + F_MS);
    float* l_s = (float*)(smc + F_LS);

    int split = blockIdx.x;
    int bh    = blockIdx.y;
    int b     = bh >> 5;
    int kv0   = split * CHUNK;
    int rows  = min(CHUNK, KVL - kv0);
    int t     = threadIdx.x;
    int lane  = t & 31;
    int wid   = t >> 5;

    // ---- Q load + convert (16x128 -> bf16 hi/lo, 272B stride) ----
    const float4* qsrc = (const float4*)(g_q + (size_t)bh * SS * DD);
#pragma unroll
    for (int i = t; i < 512; i += 256) {
        int r = i >> 5, c = i & 31;
        cvt_store_s(sb + F_QHI, sb + F_QLO, (uint32_t)(r * 272 + c * 8), qsrc[i]);
    }

    // ---- K tile: LDG -> STG copy + bf16 convert into smem ----
    float* kout = dout + K_OFF + (size_t)bh * KVL * DD;
    for (int i = t; i < rows * 32; i += 256) {
        int r = i >> 5, c = i & 31;
        int kv = kv0 + r;
        const float4* src = (kv < PASTL)
            ? (const float4*)(kcache + ((size_t)bh * PASTL + kv) * DD)
            : (const float4*)(kout + (size_t)kv * DD);
        float4 v = src[c];
        cvt_store_s(sb + F_KHI, sb + F_KLO, (uint32_t)(r * 272 + c * 8), v);
        if (kv < PASTL) ((float4*)(kout + (size_t)kv * DD))[c] = v;
    }
    for (int i = rows * 32 + t; i < CHUNK * 32; i += 256) {
        int r = i >> 5, c = i & 31;
        cvt_store_s(sb + F_KHI, sb + F_KLO, (uint32_t)(r * 272 + c * 8),
                    make_float4(0.f, 0.f, 0.f, 0.f));
    }
    __syncthreads();

    // ---- S = Q K^T on tensor cores: warp (nh: 3 natoms, kh: 4 ksteps) ----
    {
        int nh = wid & 3, kh = wid >> 2;
        float acc[3][4];
#pragma unroll
        for (int n = 0; n < 3; n++)
#pragma unroll
            for (int q = 0; q < 4; q++) acc[n][q] = 0.f;

        int a_rowin = lane & 15, a_kb = lane >> 4;
        int b_rowin = lane & 7, b_kb = (lane >> 3) & 1, b_half = (lane >> 4) & 1;
#pragma unroll
        for (int ksi = 0; ksi < 4; ksi++) {
            int k = kh * 4 + ksi;
            uint32_t aoff = (uint32_t)(a_rowin * 272 + k * 32 + a_kb * 16);
            uint32_t ah[4], al[4];
            ldsm4(ah, sb + F_QHI + aoff);
            ldsm4(al, sb + F_QLO + aoff);
            uint32_t bhf[4][2], blf[4][2];
#pragma unroll
            for (int p = 0; p < 2; p++) {
                int rowb = (3 * nh + 2 * p) * 8 + b_half * 8 + b_rowin;
                uint32_t boff = (uint32_t)(rowb * 272 + k * 32 + b_kb * 16);
                uint32_t r4[4];
                ldsm4(r4, sb + F_KHI + boff);
                bhf[2 * p][0] = r4[0]; bhf[2 * p][1] = r4[1];
                bhf[2 * p + 1][0] = r4[2]; bhf[2 * p + 1][1] = r4[3];
                ldsm4(r4, sb + F_KLO + boff);
                blf[2 * p][0] = r4[0]; blf[2 * p][1] = r4[1];
                blf[2 * p + 1][0] = r4[2]; blf[2 * p + 1][1] = r4[3];
            }
#pragma unroll
            for (int n = 0; n < 3; n++) {
                mma_bf16(acc[n], ah, bhf[n]);
                mma_bf16(acc[n], ah, blf[n]);
                mma_bf16(acc[n], al, bhf[n]);
            }
        }
        float* dst = kh ? psB : psA;
        int g = lane >> 2, tq = lane & 3;
#pragma unroll
        for (int n = 0; n < 3; n++) {
            int c0 = (3 * nh + n) * 8 + tq * 2;
            dst[g * 100 + c0]           = acc[n][0];
            dst[g * 100 + c0 + 1]       = acc[n][1];
            dst[(g + 8) * 100 + c0]     = acc[n][2];
            dst[(g + 8) * 100 + c0 + 1] = acc[n][3];
        }
    }
    __syncthreads();

    // ---- finalize: sum halves, scale, mask, rowmax, exp, rowsum ----
    const float scale = 0.08838834764831845f;  // 1/sqrt(128)
#pragma unroll
    for (int rr = 0; rr < 2; rr++) {
        int row = wid * 2 + rr;
        float vals[3];
#pragma unroll
        for (int j = 0; j < 3; j++) {
            int c = lane + 32 * j;
            int kvg = kv0 + c;
            float lg;
            if (kvg >= KVL) lg = -1e30f;
            else {
                lg = (psA[row * 100 + c] + psB[row * 100 + c]) * scale;
                if (mask[(size_t)(b * SS + row) * KVL + kvg] == 0) lg = -1e30f;
            }
            vals[j] = lg;
        }
        float m = fmaxf(fmaxf(vals[0], vals[1]), vals[2]);
#pragma unroll
        for (int o = 16; o > 0; o >>= 1)
            m = fmaxf(m, __shfl_xor_sync(0xffffffffu, m, o));
        float sum = 0.f;
#pragma unroll
        for (int j = 0; j < 3; j++) {
            float e = __expf(vals[j] - m);
            psA[row * 100 + lane + 32 * j] = e;
            sum += e;
        }
#pragma unroll
        for (int o = 16; o > 0; o >>= 1) sum += __shfl_xor_sync(0xffffffffu, sum, o);
        if (lane == 0) { m_s[row] = m; l_s[row] = sum; }
    }

    // ---- V tile: LDG -> STG copy + bf16 convert (overwrites K tile) ----
    float* vout = dout + V_OFF + (size_t)bh * KVL * DD;
    for (int i = t; i < rows * 32; i += 256) {
        int r = i >> 5, c = i & 31;
        int kv = kv0 + r;
        const float4* src = (kv < PASTL)
            ? (const float4*)(vcache + ((size_t)bh * PASTL + kv) * DD)
            : (const float4*)(vout + (size_t)kv * DD);
        float4 v = src[c];
        cvt_store_s(sb + F_KHI, sb + F_KLO, (uint32_t)(r * 272 + c * 8), v);
        if (kv < PASTL) ((float4*)(vout + (size_t)kv * DD))[c] = v;
    }
    for (int i = rows * 32 + t; i < CHUNK * 32; i += 256) {
        int r = i >> 5, c = i & 31;
        cvt_store_s(sb + F_KHI, sb + F_KLO, (uint32_t)(r * 272 + c * 8),
                    make_float4(0.f, 0.f, 0.f, 0.f));
    }
    __syncthreads();

    // ---- P convert: exp fp32 -> bf16 hi/lo, 208B row stride ----
    {
        int row = t >> 4, c0 = (t & 15) * 6;
#pragma unroll
        for (int pr = 0; pr < 3; pr++) {
            float e0 = psA[row * 100 + c0 + 2 * pr];
            float e1 = psA[row * 100 + c0 + 2 * pr + 1];
            uint32_t h;
            asm("cvt.rn.bf16x2.f32 %0, %1, %2;" : "=r"(h) : "f"(e1), "f"(e0));
            float h0 = __uint_as_float(h << 16), h1 = __uint_as_float(h & 0xFFFF0000u);
            uint32_t l;
            asm("cvt.rn.bf16x2.f32 %0, %1, %2;" : "=r"(l) : "f"(e1 - h1), "f"(e0 - h0));
            uint32_t off = (uint32_t)(row * 208 + (c0 + 2 * pr) * 2);
            *(uint32_t*)(smc + F_PHI + off) = h;
            *(uint32_t*)(smc + F_PLO + off) = l;
        }
    }
    __syncthreads();

    // ---- O = P V on tensor cores: warp (dh: 4 datoms, kh2: 3 kv-ksteps) ----
    {
        int dh = wid & 3, kh2 = wid >> 2;
        float acc2[4][4];
#pragma unroll
        for (int n = 0; n < 4; n++)
#pragma unroll
            for (int q = 0; q < 4; q++) acc2[n][q] = 0.f;

        int a_rowin = lane & 15, a_kb = lane >> 4;
        int mat = lane >> 3, mr = lane & 7;
#pragma unroll
        for (int ksi = 0; ksi < 3; ksi++) {
            int kstep = kh2 * 3 + ksi;
            uint32_t aoff = (uint32_t)(a_rowin * 208 + kstep * 32 + a_kb * 16);
            uint32_t ph[4], pl[4];
            ldsm4(ph, sb + F_PHI + aoff);
            ldsm4(pl, sb + F_PLO + aoff);
            uint32_t vhf[4][2], vlf[4][2];
#pragma unroll
            for (int p = 0; p < 2; p++) {
                int d0 = (4 * dh + 2 * p) * 8;
                int kvr = kstep * 16 + (mat & 1) * 8 + mr;
                int dcol = d0 + (mat >> 1) * 8;
                uint32_t boff = (uint32_t)(kvr * 272 + dcol * 2);
                uint32_t r4[4];
                ldsm4t(r4, sb + F_KHI + boff);
                vhf[2 * p][0] = r4[0]; vhf[2 * p][1] = r4[1];
                vhf[2 * p + 1][0] = r4[2]; vhf[2 * p + 1][1] = r4[3];
                ldsm4t(r4, sb + F_KLO + boff);
                vlf[2 * p][0] = r4[0]; vlf[2 * p][1] = r4[1];
                vlf[2 * p + 1][0] = r4[2]; vlf[2 * p + 1][1] = r4[3];
            }
#pragma unroll
            for (int n = 0; n < 4; n++) {
                mma_bf16(acc2[n], ph, vhf[n]);
                mma_bf16(acc2[n], ph, vlf[n]);
                mma_bf16(acc2[n], pl, vhf[n]);
            }
        }

        int g = lane >> 2, tq = lane & 3;
        float* obuf = (float*)(smc + F_QHI);   // Q dead: 16x128 fp32 buffer
        if (kh2 == 0) {
#pragma unroll
            for (int n = 0; n < 4; n++) {
                int c0 = (4 * dh + n) * 8 + tq * 2;
                obuf[g * 128 + c0]           = acc2[n][0];
                obuf[g * 128 + c0 + 1]       = acc2[n][1];
                obuf[(g + 8) * 128 + c0]     = acc2[n][2];
                obuf[(g + 8) * 128 + c0 + 1] = acc2[n][3];
            }
        }
        __syncthreads();
        if (kh2 == 1) {
            size_t base = ((size_t)split * 256 + bh) * (SS * DD);
#pragma unroll
            for (int n = 0; n < 4; n++) {
                int c0 = (4 * dh + n) * 8 + tq * 2;
#pragma unroll
                for (int half = 0; half < 2; half++) {
                    int srow = g + half * 8;
                    float2 o = make_float2(
                        acc2[n][2 * half]     + obuf[srow * 128 + c0],
                        acc2[n][2 * half + 1] + obuf[srow * 128 + c0 + 1]);
                    *(float2*)(g_pacc + base + (size_t)srow * DD + c0) = o;
                }
            }
        }
    }
    if (t < 16) {
        size_t idx = ((size_t)split * 256 + bh) * SS + t;
        g_pm[idx] = m_s[t];
        g_pl[idx] = l_s[t];
    }
}

// ---------------------------------------------------------------------------
// Combine split partials -> g_attn. Grid 256 (bh), 512 threads (s, dg).
// ---------------------------------------------------------------------------
__global__ __launch_bounds__(512) void combine_k()
{
    int bh = blockIdx.x;
    int t  = threadIdx.x;
    int dg = t & 31, s = t >> 5;
    int b = bh >> 5, h = bh & 31;

    float M = -3.4e38f;
#pragma unroll 11
    for (int sp = 0; sp < NSPLIT; sp++)
        M = fmaxf(M, g_pm[((size_t)sp * 256 + bh) * SS + s]);
    float lsum = 0.f;
    float4 o = make_float4(0.f, 0.f, 0.f, 0.f);
#pragma unroll 11
    for (int sp = 0; sp < NSPLIT; sp++) {
        size_t idx = (size_t)sp * 256 + bh;
        float f = __expf(g_pm[idx * SS + s] - M);
        lsum += f * g_pl[idx * SS + s];
        float4 a = ((const float4*)(g_pacc + idx * (SS * DD) + (size_t)s * DD))[dg];
        o.x += f * a.x; o.y += f * a.y; o.z += f * a.z; o.w += f * a.w;
    }
    float inv = 1.0f / lsum;
    o.x *= inv; o.y *= inv; o.z *= inv; o.w *= inv;
    ((float4*)(g_attn + ((size_t)(b * SS + s)) * HD + h * DD))[dg] = o;
}

// ---------------------------------------------------------------------------
extern "C" void kernel_launch(void* const* d_in, const int* in_sizes, int n_in,
                              void* d_out, int out_size)
{
    const float* hidden = (const float*)d_in[0];
    const int*   mask   = (const int*)d_in[1];
    const float* kcache = (const float*)d_in[2];
    const float* vcache = (const float*)d_in[3];
    const float* Wq     = (const float*)d_in[4];
    const float* Wk     = (const float*)d_in[5];
    const float* Wv     = (const float*)d_in[6];
    const float* Wo     = (const float*)d_in[7];
    float* out = (float*)d_out;

    const int FLASH_SMEM = 74112;
    const int SM128 = 1024 + 2 * (128 * 32 * 4 + 128 * 32 * 4) + 4 * 128 * 80;
    const int SM64  = 1024 + 2 * (128 * 32 * 4 + 64 * 32 * 4)
                    + 2 * 128 * 80 + 2 * 64 * 80;
    cudaFuncSetAttribute(flash_k, cudaFuncAttributeMaxDynamicSharedMemorySize,
                         FLASH_SMEM);
    cudaFuncSetAttribute((gemm_mma<128, KS_QKV>),
                         cudaFuncAttributeMaxDynamicSharedMemorySize, SM128);
    cudaFuncSetAttribute((gemm_mma<64, KS_O>),
                         cudaFuncAttributeMaxDynamicSharedMemorySize, SM64);

    // 1. QKV projections (NT=128, split-K=3)
    gemm_mma<128, KS_QKV><<<dim3(96, KS_QKV), 256, SM128>>>(
        hidden, Wq, Wk, Wv, 12288, -1);
    // 2+3. Reduce + route in two half-launches (flash stays launch #4)
    reduce_qkv_k<<<768, 256>>>(out, 0);
    reduce_qkv_k<<<768, 256>>>(out, 196608);
    // 4. Tensor-core flash attention + fused K/V cache copies
    flash_k<<<dim3(NSPLIT, 256), 256, FLASH_SMEM>>>(kcache, vcache, mask, out);
    // 5. Combine flash partials
    combine_k<<<256, 512>>>();
    // 6. Output projection (NT=64, split-K=4)
    gemm_mma<64, KS_O><<<dim3(64, KS_O), 256, SM64>>>(
        nullptr, Wo, Wo, Wo, 4096, 3);
    reduce_o_k<<<512, 256>>>(out);
}